// round 6
// baseline (speedup 1.0000x reference)
#include <cuda_runtime.h>

// S4D exact diagonal recurrence. R6 = R5 + software-pipelined u-broadcast:
// all 32 SHFLs of a tile are issued back-to-back into a register array BEFORE
// the FMA loop, removing the 26-cycle SHFL latency from every step's
// dependency chain (R5's issue was 41.8%, per-warp IPC 0.17 because the
// just-in-time SHFL serialized each step to ~30 cycles).

constexpr int Hh = 256;
constexpr int N2 = 32;
constexpr int Bb = 16;
constexpr int Ll = 8192;
constexpr int WPB  = 4;       // warps per block
constexpr int TILE = 32;
constexpr int STR  = 36;      // smem row stride (floats): conflict-free

using u64 = unsigned long long;

__device__ __forceinline__ u64 pack2(float lo, float hi) {
    u64 r;
    asm("mov.b64 %0, {%1, %2};" : "=l"(r) : "f"(lo), "f"(hi));
    return r;
}
__device__ __forceinline__ void unpack2(u64 v, float& lo, float& hi) {
    asm("mov.b64 {%0, %1}, %2;" : "=f"(lo), "=f"(hi) : "l"(v));
}
__device__ __forceinline__ u64 fma2(u64 a, u64 b, u64 c) {
    u64 d;
    asm("fma.rn.f32x2 %0, %1, %2, %3;" : "=l"(d) : "l"(a), "l"(b), "l"(c));
    return d;
}
__device__ __forceinline__ u64 mul2(u64 a, u64 b) {
    u64 d;
    asm("mul.rn.f32x2 %0, %1, %2;" : "=l"(d) : "l"(a), "l"(b));
    return d;
}

__global__ __launch_bounds__(WPB * 32, 1)
void s4d_r6(const float* __restrict__ u,
            const float* __restrict__ log_dt,
            const float* __restrict__ log_A_real,
            const float* __restrict__ A_imag,
            const float* __restrict__ C,
            const float* __restrict__ D,
            float* __restrict__ y)
{
    __shared__ float sm[WPB][TILE][STR];

    const int warp = threadIdx.x >> 5;
    const int lane = threadIdx.x & 31;
    const int s    = lane >> 4;            // which of the warp's 2 sequences
    const int j    = lane & 15;            // mode-pair index / output column

    const int W = blockIdx.x * WPB + warp;
    const int g = 2 * W + s;               // g = b*H + h
    const int h = g & (Hh - 1);

    // ---- per-lane parameters for modes n = 2j, 2j+1 of head h ----
    const float dt = expf(log_dt[h]);
    const float d  = D[h];

    float wr[2], wi[2], Ctr[2], nCti[2];
    #pragma unroll
    for (int k = 0; k < 2; ++k) {
        const int n = 2 * j + k;
        const float ar = -expf(log_A_real[h * N2 + n]);
        const float ai = A_imag[h * N2 + n];
        const float mag = expf(ar * dt);
        wr[k] = mag * cosf(ai * dt);
        wi[k] = mag * sinf(ai * dt);
        const float na = ar * ar + ai * ai;
        const float tr = wr[k] - 1.0f, ti = wi[k];
        const float qr = (tr * ar + ti * ai) / na;
        const float qi = (ti * ar - tr * ai) / na;
        const float cr = C[(h * N2 + n) * 2 + 0];
        const float ci = C[(h * N2 + n) * 2 + 1];
        Ctr[k]  =  2.0f * (cr * qr - ci * qi);
        nCti[k] = -2.0f * (cr * qi + ci * qr);
    }
    const u64 WR2   = pack2(wr[0],   wr[1]);
    const u64 WI2   = pack2(wi[0],   wi[1]);
    const u64 NWI2  = pack2(-wi[0], -wi[1]);
    const u64 CTR2  = pack2(Ctr[0],  Ctr[1]);
    const u64 NCTI2 = pack2(nCti[0], nCti[1]);

    u64 XR = pack2(0.0f, 0.0f);
    u64 XI = pack2(0.0f, 0.0f);

    const float* __restrict__ up = u + (size_t)g * Ll;
    float*       __restrict__ yp = y + (size_t)g * Ll;

    // lane (s,j) holds u[base+2j], u[base+2j+1] of its sequence (LDG.64).
    float2 uv = *reinterpret_cast<const float2*>(up + 2 * j);

    for (int base = 0; base < Ll; base += TILE) {
        // prefetch next tile's u (covers DRAM latency across the tile body)
        float2 uv_next;
        {
            const int nb = (base + TILE < Ll) ? (base + TILE) : 0;
            uv_next = *reinterpret_cast<const float2*>(up + nb + 2 * j);
        }

        // ---- phase 1: all 32 broadcasts, independent, pipelined ----
        float ubuf[TILE];
        #pragma unroll
        for (int t = 0; t < TILE; ++t) {
            const float src = (t & 1) ? uv.y : uv.x;
            ubuf[t] = __shfl_sync(0xffffffffu, src, (lane & 16) | (t >> 1));
        }

        // ---- phase 2: recurrence; chain = 2 dependent packed FMAs ----
        #pragma unroll
        for (int t = 0; t < TILE; ++t) {
            const u64 U2  = pack2(ubuf[t], ubuf[t]);
            const u64 t1  = fma2(NWI2, XI, U2);
            const u64 t2  = mul2(WR2,  XI);
            const u64 nXR = fma2(WR2,  XR, t1);
            XI = fma2(WI2, XR, t2);
            XR = nXR;

            u64 q = mul2(CTR2, XR);
            q = fma2(NCTI2, XI, q);
            float qlo, qhi;
            unpack2(q, qlo, qhi);
            sm[warp][t][lane] = qlo + qhi;   // conflict-free
        }
        __syncwarp();

        // ---- phase 3: transpose-reduce; lane (s,j) -> outputs 2j, 2j+1 ----
        {
            float2 out;
            #pragma unroll
            for (int q2 = 0; q2 < 2; ++q2) {
                const int t2 = 2 * j + q2;
                const float4* r4 =
                    reinterpret_cast<const float4*>(&sm[warp][t2][16 * s]);
                const float4 a0 = r4[0], a1 = r4[1], a2 = r4[2], a3 = r4[3];
                const float sum = (((a0.x + a0.y) + (a0.z + a0.w))
                                 + ((a1.x + a1.y) + (a1.z + a1.w)))
                                + (((a2.x + a2.y) + (a2.z + a2.w))
                                 + ((a3.x + a3.y) + (a3.z + a3.w)));
                (&out.x)[q2] = fmaf(d, q2 ? uv.y : uv.x, sum);
            }
            *reinterpret_cast<float2*>(yp + base + 2 * j) = out;
        }
        __syncwarp();

        uv = uv_next;
    }
}

extern "C" void kernel_launch(void* const* d_in, const int* in_sizes, int n_in,
                              void* d_out, int out_size)
{
    const float* u          = (const float*)d_in[0];
    const float* log_dt     = (const float*)d_in[1];
    const float* log_A_real = (const float*)d_in[2];
    const float* A_imag     = (const float*)d_in[3];
    const float* C          = (const float*)d_in[4];
    const float* D          = (const float*)d_in[5];
    float* y = (float*)d_out;

    const int seqs = Bb * Hh;                      // 4096 sequences
    const int grid = seqs / (2 * WPB);             // 512 blocks of 4 warps
    s4d_r6<<<grid, WPB * 32>>>(u, log_dt, log_A_real, A_imag, C, D, y);
}